// round 2
// baseline (speedup 1.0000x reference)
#include <cuda_runtime.h>

#define NN 200000
#define EE 400000
#define DD 128
#define LL 5
#define BN_EPS 1e-5f

#define HS_STRIDE 132
#define GEMM_SMEM ((128 * HS_STRIDE + 64 * HS_STRIDE) * 4)
#define COMBINE_BLOCKS 1184

// ---------------- scratch (static device globals; no allocation) ----------------
__device__ float g_h[(size_t)NN * DD];     // h_prev
__device__ float g_hl[(size_t)NN * DD];    // linear output per layer
__device__ float g_agg[(size_t)NN * DD];   // scatter accumulator / out_pre
__device__ float g_ee[(size_t)EE * DD];    // edge embeddings
__device__ float g_norm[EE];
__device__ float g_deg[NN];
__device__ float g_dis[NN];
__device__ float g_invdeg[NN];
__device__ double g_sum[DD];
__device__ double g_sq[DD];
__device__ float g_scale[DD];
__device__ float g_shift[DD];

// ---------------- encoders ----------------
__global__ void k_node_enc(const int* __restrict__ x,
                           const float* __restrict__ at,
                           float* __restrict__ out) {
    int node = blockIdx.x * 8 + (threadIdx.x >> 5);
    if (node >= NN) return;
    int lane = threadIdx.x & 31;
    float4 acc = make_float4(0.f, 0.f, 0.f, 0.f);
#pragma unroll
    for (int c = 0; c < 9; c++) {
        int idx = x[node * 9 + c];
        const float4* t = (const float4*)(at + ((size_t)c * 100 + idx) * DD);
        float4 v = t[lane];
        acc.x += v.x; acc.y += v.y; acc.z += v.z; acc.w += v.w;
    }
    size_t o = (size_t)node * 32 + lane;
    ((float4*)g_h)[o] = acc;
    ((float4*)out)[o] = acc;
}

__global__ void k_deg_init() {
    int i = blockIdx.x * blockDim.x + threadIdx.x;
    if (i < NN) g_deg[i] = 1.0f;
}

__global__ void k_deg_count(const int* __restrict__ ei) {
    int e = blockIdx.x * blockDim.x + threadIdx.x;
    if (e < EE) atomicAdd(&g_deg[ei[e]], 1.0f);
}

__global__ void k_dis() {
    int i = blockIdx.x * blockDim.x + threadIdx.x;
    if (i < NN) {
        float d = g_deg[i];
        g_dis[i] = rsqrtf(d);
        g_invdeg[i] = 1.0f / d;
    }
}

__global__ void k_edge_enc(const int* __restrict__ ei,
                           const int* __restrict__ attr,
                           const float* __restrict__ bt) {
    int e = blockIdx.x * 8 + (threadIdx.x >> 5);
    if (e >= EE) return;
    int lane = threadIdx.x & 31;
    float4 acc = make_float4(0.f, 0.f, 0.f, 0.f);
#pragma unroll
    for (int c = 0; c < 3; c++) {
        int idx = attr[e * 3 + c];
        const float4* t = (const float4*)(bt + ((size_t)c * 10 + idx) * DD);
        float4 v = t[lane];
        acc.x += v.x; acc.y += v.y; acc.z += v.z; acc.w += v.w;
    }
    ((float4*)g_ee)[(size_t)e * 32 + lane] = acc;
    if (lane == 0) g_norm[e] = g_dis[ei[e]] * g_dis[ei[EE + e]];
}

// ---------------- GEMM: hl = h_prev @ W^T + b (f32x2 packed FMA) ----------------
__global__ __launch_bounds__(256, 2)
void k_gemm(const float* __restrict__ Wl, const float* __restrict__ bl) {
    extern __shared__ float smem[];
    float* hs = smem;                    // [128][HS_STRIDE]
    float* ws = smem + 128 * HS_STRIDE;  // [64][HS_STRIDE]
    int tid = threadIdx.x;
    int row0 = blockIdx.x * 128;
    int cb = blockIdx.y;  // column half: cols cb*64 .. cb*64+63

    const float4* Wg4 = (const float4*)(Wl + (size_t)cb * 64 * DD);
    for (int i = tid; i < 64 * 32; i += 256) {
        int c = i >> 5, k4 = i & 31;
        float4 v = Wg4[i];
        *(float4*)&ws[c * HS_STRIDE + k4 * 4] = v;
    }
    const float4* hg4 = (const float4*)g_h;
    for (int i = tid; i < 128 * 32; i += 256) {
        int r = i >> 5, k4 = i & 31;
        int rg = row0 + r;
        float4 v = (rg < NN) ? hg4[(size_t)rg * 32 + k4] : make_float4(0.f, 0.f, 0.f, 0.f);
        *(float4*)&hs[r * HS_STRIDE + k4 * 4] = v;
    }
    __syncthreads();

    int tx = tid & 15, ty = tid >> 4;
    unsigned long long acc[8][4];
#pragma unroll
    for (int i = 0; i < 8; i++)
#pragma unroll
        for (int j = 0; j < 4; j++) acc[i][j] = 0ULL;

#pragma unroll 4
    for (int k = 0; k < 128; k += 2) {
        unsigned long long hv[8], wv[4];
#pragma unroll
        for (int i = 0; i < 8; i++)
            hv[i] = *(const unsigned long long*)&hs[(ty + 16 * i) * HS_STRIDE + k];
#pragma unroll
        for (int j = 0; j < 4; j++)
            wv[j] = *(const unsigned long long*)&ws[(tx + 16 * j) * HS_STRIDE + k];
#pragma unroll
        for (int i = 0; i < 8; i++)
#pragma unroll
            for (int j = 0; j < 4; j++)
                asm("fma.rn.f32x2 %0, %1, %2, %0;"
                    : "+l"(acc[i][j]) : "l"(hv[i]), "l"(wv[j]));
    }

    float bj[4];
#pragma unroll
    for (int j = 0; j < 4; j++) bj[j] = bl[cb * 64 + tx + 16 * j];

#pragma unroll
    for (int i = 0; i < 8; i++) {
        int r = row0 + ty + 16 * i;
        if (r < NN) {
#pragma unroll
            for (int j = 0; j < 4; j++) {
                float lo, hi;
                asm("mov.b64 {%0, %1}, %2;" : "=f"(lo), "=f"(hi) : "l"(acc[i][j]));
                g_hl[(size_t)r * DD + cb * 64 + tx + 16 * j] = lo + hi + bj[j];
            }
        }
    }
}

// ---------------- per-layer helpers ----------------
__global__ void k_zero_agg() {
    int i = blockIdx.x * blockDim.x + threadIdx.x;  // over NN*32 float4s
    ((float4*)g_agg)[i] = make_float4(0.f, 0.f, 0.f, 0.f);
}

__global__ void k_zero_stats() {
    int c = threadIdx.x;
    g_sum[c] = 0.0;
    g_sq[c] = 0.0;
}

__global__ void k_msg(const int* __restrict__ ei) {
    int e = blockIdx.x * 8 + (threadIdx.x >> 5);
    if (e >= EE) return;
    int lane = threadIdx.x & 31;
    int r = ei[e];
    int c = ei[EE + e];
    float nrm = g_norm[e];
    float4 h = ((const float4*)g_hl)[(size_t)r * 32 + lane];
    float4 em = ((const float4*)g_ee)[(size_t)e * 32 + lane];
    float mx = nrm * fmaxf(h.x + em.x, 0.f);
    float my = nrm * fmaxf(h.y + em.y, 0.f);
    float mz = nrm * fmaxf(h.z + em.z, 0.f);
    float mw = nrm * fmaxf(h.w + em.w, 0.f);
    float* dst = g_agg + (size_t)c * DD + lane * 4;
    asm volatile("red.global.add.v4.f32 [%0], {%1, %2, %3, %4};"
                 :: "l"(dst), "f"(mx), "f"(my), "f"(mz), "f"(mw) : "memory");
}

// out_pre = agg + relu(hl + root)/deg  (stored back into g_agg) + BN stats
__global__ void k_combine(const float* __restrict__ rootl) {
    int tid = threadIdx.x;
    int lane = tid & 31;
    int rg = tid >> 5;
    float4 r4 = ((const float4*)rootl)[lane];
    float s0 = 0.f, s1 = 0.f, s2 = 0.f, s3 = 0.f;
    float q0 = 0.f, q1 = 0.f, q2 = 0.f, q3 = 0.f;
    float4* agg4 = (float4*)g_agg;
    const float4* hl4 = (const float4*)g_hl;
    for (int n = blockIdx.x * 8 + rg; n < NN; n += gridDim.x * 8) {
        float4 a = agg4[(size_t)n * 32 + lane];
        float4 h = hl4[(size_t)n * 32 + lane];
        float idg = g_invdeg[n];
        float4 o;
        o.x = fmaf(fmaxf(h.x + r4.x, 0.f), idg, a.x);
        o.y = fmaf(fmaxf(h.y + r4.y, 0.f), idg, a.y);
        o.z = fmaf(fmaxf(h.z + r4.z, 0.f), idg, a.z);
        o.w = fmaf(fmaxf(h.w + r4.w, 0.f), idg, a.w);
        agg4[(size_t)n * 32 + lane] = o;
        s0 += o.x; s1 += o.y; s2 += o.z; s3 += o.w;
        q0 += o.x * o.x; q1 += o.y * o.y; q2 += o.z * o.z; q3 += o.w * o.w;
    }
    __shared__ float sh[256][4];
    sh[tid][0] = s0; sh[tid][1] = s1; sh[tid][2] = s2; sh[tid][3] = s3;
    __syncthreads();
    if (rg == 0) {
        float t0 = 0.f, t1 = 0.f, t2 = 0.f, t3 = 0.f;
#pragma unroll
        for (int g = 0; g < 8; g++) {
            t0 += sh[g * 32 + lane][0];
            t1 += sh[g * 32 + lane][1];
            t2 += sh[g * 32 + lane][2];
            t3 += sh[g * 32 + lane][3];
        }
        atomicAdd(&g_sum[lane * 4 + 0], (double)t0);
        atomicAdd(&g_sum[lane * 4 + 1], (double)t1);
        atomicAdd(&g_sum[lane * 4 + 2], (double)t2);
        atomicAdd(&g_sum[lane * 4 + 3], (double)t3);
    }
    __syncthreads();
    sh[tid][0] = q0; sh[tid][1] = q1; sh[tid][2] = q2; sh[tid][3] = q3;
    __syncthreads();
    if (rg == 0) {
        float t0 = 0.f, t1 = 0.f, t2 = 0.f, t3 = 0.f;
#pragma unroll
        for (int g = 0; g < 8; g++) {
            t0 += sh[g * 32 + lane][0];
            t1 += sh[g * 32 + lane][1];
            t2 += sh[g * 32 + lane][2];
            t3 += sh[g * 32 + lane][3];
        }
        atomicAdd(&g_sq[lane * 4 + 0], (double)t0);
        atomicAdd(&g_sq[lane * 4 + 1], (double)t1);
        atomicAdd(&g_sq[lane * 4 + 2], (double)t2);
        atomicAdd(&g_sq[lane * 4 + 3], (double)t3);
    }
}

__global__ void k_bn_prep(const float* __restrict__ gammal,
                          const float* __restrict__ betal) {
    int c = threadIdx.x;
    double mean = g_sum[c] / (double)NN;
    double var = g_sq[c] / (double)NN - mean * mean;
    if (var < 0.0) var = 0.0;
    float inv = rsqrtf((float)var + BN_EPS);
    float sc = gammal[c] * inv;
    g_scale[c] = sc;
    g_shift[c] = betal[c] - (float)mean * sc;
}

__global__ void k_bn_apply(float* __restrict__ out, int do_relu) {
    int idx = blockIdx.x * blockDim.x + threadIdx.x;  // over NN*32 float4s
    int lane = idx & 31;
    float4 x = ((const float4*)g_agg)[idx];
    float4 sc = ((const float4*)g_scale)[lane];
    float4 sf = ((const float4*)g_shift)[lane];
    float4 v;
    v.x = fmaf(x.x, sc.x, sf.x);
    v.y = fmaf(x.y, sc.y, sf.y);
    v.z = fmaf(x.z, sc.z, sf.z);
    v.w = fmaf(x.w, sc.w, sf.w);
    if (do_relu) {
        v.x = fmaxf(v.x, 0.f); v.y = fmaxf(v.y, 0.f);
        v.z = fmaxf(v.z, 0.f); v.w = fmaxf(v.w, 0.f);
    }
    ((float4*)g_h)[idx] = v;
    float4 t = ((float4*)out)[idx];
    t.x += v.x; t.y += v.y; t.z += v.z; t.w += v.w;
    ((float4*)out)[idx] = t;
}

// ---------------- launch ----------------
extern "C" void kernel_launch(void* const* d_in, const int* in_sizes, int n_in,
                              void* d_out, int out_size) {
    const int*   x     = (const int*)d_in[0];
    const int*   ei    = (const int*)d_in[1];
    const int*   attr  = (const int*)d_in[2];
    const float* at    = (const float*)d_in[3];
    const float* bt    = (const float*)d_in[4];
    const float* W     = (const float*)d_in[5];
    const float* b     = (const float*)d_in[6];
    const float* root  = (const float*)d_in[7];
    const float* gamma = (const float*)d_in[8];
    const float* beta  = (const float*)d_in[9];
    float* out = (float*)d_out;

    cudaFuncSetAttribute(k_gemm, cudaFuncAttributeMaxDynamicSharedMemorySize, GEMM_SMEM);

    k_node_enc<<<NN / 8, 256>>>(x, at, out);
    k_deg_init<<<(NN + 255) / 256, 256>>>();
    k_deg_count<<<(EE + 255) / 256, 256>>>(ei);
    k_dis<<<(NN + 255) / 256, 256>>>();
    k_edge_enc<<<EE / 8, 256>>>(ei, attr, bt);

    for (int l = 0; l < LL; l++) {
        k_zero_agg<<<NN * 32 / 256, 256>>>();
        k_zero_stats<<<1, 128>>>();
        k_gemm<<<dim3((NN + 127) / 128, 2), 256, GEMM_SMEM>>>(W + (size_t)l * DD * DD,
                                                              b + (size_t)l * DD);
        k_msg<<<EE / 8, 256>>>(ei);
        k_combine<<<COMBINE_BLOCKS, 256>>>(root + (size_t)l * DD);
        k_bn_prep<<<1, 128>>>(gamma + (size_t)l * DD, beta + (size_t)l * DD);
        k_bn_apply<<<NN * 32 / 256, 256>>>(out, l < LL - 1 ? 1 : 0);
    }
}

// round 3
// speedup vs baseline: 1.3414x; 1.3414x over previous
#include <cuda_runtime.h>

#define NN 200000
#define EE 400000
#define DD 128
#define LL 5
#define BN_EPS 1e-5f

#define AS 132                         // padded smem stride (words)
#define GEMM_SMEM ((64 * AS + 128 * AS) * 4)
#define STATS_BLOCKS 1184

// ---------------- scratch (static device globals; no allocation) ----------------
__device__ float g_h[(size_t)NN * DD];     // layer input (post-BN)
__device__ float g_hl[(size_t)NN * DD];    // linear output
__device__ float g_agg[(size_t)NN * DD];   // relu(hl+root)/deg + scatter accum
__device__ float g_ee[(size_t)EE * DD];    // edge embeddings
__device__ float g_norm[EE];
__device__ float g_deg[NN];
__device__ float g_dis[NN];
__device__ float g_invdeg[NN];
__device__ double g_sum[DD];
__device__ double g_sq[DD];
__device__ float g_scale[DD];
__device__ float g_shift[DD];

// ---------------- encoders / setup ----------------
__global__ void k_node_enc(const int* __restrict__ x,
                           const float* __restrict__ at,
                           float* __restrict__ out) {
    int node = blockIdx.x * 8 + (threadIdx.x >> 5);
    if (node >= NN) return;
    int lane = threadIdx.x & 31;
    float4 acc = make_float4(0.f, 0.f, 0.f, 0.f);
#pragma unroll
    for (int c = 0; c < 9; c++) {
        int idx = x[node * 9 + c];
        const float4* t = (const float4*)(at + ((size_t)c * 100 + idx) * DD);
        float4 v = t[lane];
        acc.x += v.x; acc.y += v.y; acc.z += v.z; acc.w += v.w;
    }
    size_t o = (size_t)node * 32 + lane;
    ((float4*)g_h)[o] = acc;
    ((float4*)out)[o] = acc;
}

__global__ void k_deg_init() {
    int i = blockIdx.x * blockDim.x + threadIdx.x;
    if (i < NN) g_deg[i] = 1.0f;
}

__global__ void k_deg_count(const int* __restrict__ ei) {
    int e = blockIdx.x * blockDim.x + threadIdx.x;
    if (e < EE) atomicAdd(&g_deg[ei[e]], 1.0f);
}

__global__ void k_dis() {
    int i = blockIdx.x * blockDim.x + threadIdx.x;
    if (i < NN) {
        float d = g_deg[i];
        g_dis[i] = rsqrtf(d);
        g_invdeg[i] = 1.0f / d;
    }
}

__global__ void k_edge_enc(const int* __restrict__ ei,
                           const int* __restrict__ attr,
                           const float* __restrict__ bt) {
    int e = blockIdx.x * 8 + (threadIdx.x >> 5);
    if (e >= EE) return;
    int lane = threadIdx.x & 31;
    float4 acc = make_float4(0.f, 0.f, 0.f, 0.f);
#pragma unroll
    for (int c = 0; c < 3; c++) {
        int idx = attr[e * 3 + c];
        const float4* t = (const float4*)(bt + ((size_t)c * 10 + idx) * DD);
        float4 v = t[lane];
        acc.x += v.x; acc.y += v.y; acc.z += v.z; acc.w += v.w;
    }
    ((float4*)g_ee)[(size_t)e * 32 + lane] = acc;
    if (lane == 0) g_norm[e] = g_dis[ei[e]] * g_dis[ei[EE + e]];
}

// ---------------- GEMM (tf32 mma.sync) + fused combine epilogue ----------------
// hl = h @ W^T + b ;  agg = relu(hl + root) * invdeg
// Block: 64 rows x 128 cols, K=128. 8 warps, warp tile 16x64.
__global__ __launch_bounds__(256, 2)
void k_gemm(const float* __restrict__ Wl, const float* __restrict__ bl,
            const float* __restrict__ rootl) {
    extern __shared__ unsigned smem_u[];
    unsigned* As = smem_u;             // [64][AS]
    unsigned* Bs = smem_u + 64 * AS;   // [128][AS]
    int tid = threadIdx.x;
    int row0 = blockIdx.x * 64;        // NN = 64 * 3125 exactly

    if (blockIdx.x == 0 && tid < DD) { g_sum[tid] = 0.0; g_sq[tid] = 0.0; }

    // stage A (h rows, fp32 -> tf32)
    const float4* hg4 = (const float4*)g_h + (size_t)row0 * 32;
    for (int i = tid; i < 64 * 32; i += 256) {
        int r = i >> 5, c4 = i & 31;
        float4 v = hg4[(size_t)r * 32 + c4];
        unsigned u0, u1, u2, u3;
        asm("cvt.rna.tf32.f32 %0, %1;" : "=r"(u0) : "f"(v.x));
        asm("cvt.rna.tf32.f32 %0, %1;" : "=r"(u1) : "f"(v.y));
        asm("cvt.rna.tf32.f32 %0, %1;" : "=r"(u2) : "f"(v.z));
        asm("cvt.rna.tf32.f32 %0, %1;" : "=r"(u3) : "f"(v.w));
        *(uint4*)&As[r * AS + c4 * 4] = make_uint4(u0, u1, u2, u3);
    }
    // stage B (W rows: Bs[n][k] = W[n][k])
    const float4* Wg4 = (const float4*)Wl;
    for (int i = tid; i < 128 * 32; i += 256) {
        int n = i >> 5, c4 = i & 31;
        float4 v = Wg4[i];
        unsigned u0, u1, u2, u3;
        asm("cvt.rna.tf32.f32 %0, %1;" : "=r"(u0) : "f"(v.x));
        asm("cvt.rna.tf32.f32 %0, %1;" : "=r"(u1) : "f"(v.y));
        asm("cvt.rna.tf32.f32 %0, %1;" : "=r"(u2) : "f"(v.z));
        asm("cvt.rna.tf32.f32 %0, %1;" : "=r"(u3) : "f"(v.w));
        *(uint4*)&Bs[n * AS + c4 * 4] = make_uint4(u0, u1, u2, u3);
    }
    __syncthreads();

    int w = tid >> 5, lane = tid & 31;
    int g = lane >> 2, tig = lane & 3;
    int rbase = (w & 3) * 16;          // warp row tile within 64
    int cbase = (w >> 2) * 64;         // warp col tile within 128

    float acc[8][4];
#pragma unroll
    for (int j = 0; j < 8; j++)
#pragma unroll
        for (int q = 0; q < 4; q++) acc[j][q] = 0.f;

#pragma unroll
    for (int ks = 0; ks < 16; ks++) {
        int k0 = ks * 8;
        unsigned a0 = As[(rbase + g) * AS + k0 + tig];
        unsigned a1 = As[(rbase + g + 8) * AS + k0 + tig];
        unsigned a2 = As[(rbase + g) * AS + k0 + tig + 4];
        unsigned a3 = As[(rbase + g + 8) * AS + k0 + tig + 4];
#pragma unroll
        for (int j = 0; j < 8; j++) {
            unsigned b0 = Bs[(cbase + j * 8 + g) * AS + k0 + tig];
            unsigned b1 = Bs[(cbase + j * 8 + g) * AS + k0 + tig + 4];
            asm("mma.sync.aligned.m16n8k8.row.col.f32.tf32.tf32.f32 "
                "{%0,%1,%2,%3},{%4,%5,%6,%7},{%8,%9},{%0,%1,%2,%3};"
                : "+f"(acc[j][0]), "+f"(acc[j][1]), "+f"(acc[j][2]), "+f"(acc[j][3])
                : "r"(a0), "r"(a1), "r"(a2), "r"(a3), "r"(b0), "r"(b1));
        }
    }

    // epilogue: bias, write hl; agg = relu(hl+root)*invdeg
    int r0g = row0 + rbase + g;        // rows for acc[.][0,1]
    int r1g = r0g + 8;                 // rows for acc[.][2,3]
    float id0 = g_invdeg[r0g];
    float id1 = g_invdeg[r1g];
#pragma unroll
    for (int j = 0; j < 8; j++) {
        int c0 = cbase + j * 8 + tig * 2;
        float bb0 = bl[c0], bb1 = bl[c0 + 1];
        float rr0 = rootl[c0], rr1 = rootl[c0 + 1];
        float h00 = acc[j][0] + bb0, h01 = acc[j][1] + bb1;
        float h10 = acc[j][2] + bb0, h11 = acc[j][3] + bb1;
        *(float2*)&g_hl[(size_t)r0g * DD + c0] = make_float2(h00, h01);
        *(float2*)&g_hl[(size_t)r1g * DD + c0] = make_float2(h10, h11);
        float2 v0 = make_float2(fmaxf(h00 + rr0, 0.f) * id0,
                                fmaxf(h01 + rr1, 0.f) * id0);
        float2 v1 = make_float2(fmaxf(h10 + rr0, 0.f) * id1,
                                fmaxf(h11 + rr1, 0.f) * id1);
        *(float2*)&g_agg[(size_t)r0g * DD + c0] = v0;
        *(float2*)&g_agg[(size_t)r1g * DD + c0] = v1;
    }
}

// ---------------- message: agg[col] += norm * relu(hl[row] + ee) ----------------
__global__ void k_msg(const int* __restrict__ ei) {
    int e = blockIdx.x * 8 + (threadIdx.x >> 5);
    if (e >= EE) return;
    int lane = threadIdx.x & 31;
    int r = ei[e];
    int c = ei[EE + e];
    float nrm = g_norm[e];
    float4 h = ((const float4*)g_hl)[(size_t)r * 32 + lane];
    float4 em = ((const float4*)g_ee)[(size_t)e * 32 + lane];
    float mx = nrm * fmaxf(h.x + em.x, 0.f);
    float my = nrm * fmaxf(h.y + em.y, 0.f);
    float mz = nrm * fmaxf(h.z + em.z, 0.f);
    float mw = nrm * fmaxf(h.w + em.w, 0.f);
    float* dst = g_agg + (size_t)c * DD + lane * 4;
    asm volatile("red.global.add.v4.f32 [%0], {%1, %2, %3, %4};"
                 :: "l"(dst), "f"(mx), "f"(my), "f"(mz), "f"(mw) : "memory");
}

// ---------------- BN statistics over g_agg ----------------
__global__ void k_stats() {
    int tid = threadIdx.x;
    int lane = tid & 31;
    int rg = tid >> 5;
    float s0 = 0.f, s1 = 0.f, s2 = 0.f, s3 = 0.f;
    float q0 = 0.f, q1 = 0.f, q2 = 0.f, q3 = 0.f;
    const float4* agg4 = (const float4*)g_agg;
    for (int n = blockIdx.x * 8 + rg; n < NN; n += gridDim.x * 8) {
        float4 o = agg4[(size_t)n * 32 + lane];
        s0 += o.x; s1 += o.y; s2 += o.z; s3 += o.w;
        q0 += o.x * o.x; q1 += o.y * o.y; q2 += o.z * o.z; q3 += o.w * o.w;
    }
    __shared__ float sh[256][4];
    sh[tid][0] = s0; sh[tid][1] = s1; sh[tid][2] = s2; sh[tid][3] = s3;
    __syncthreads();
    if (rg == 0) {
        float t0 = 0.f, t1 = 0.f, t2 = 0.f, t3 = 0.f;
#pragma unroll
        for (int g = 0; g < 8; g++) {
            t0 += sh[g * 32 + lane][0];
            t1 += sh[g * 32 + lane][1];
            t2 += sh[g * 32 + lane][2];
            t3 += sh[g * 32 + lane][3];
        }
        atomicAdd(&g_sum[lane * 4 + 0], (double)t0);
        atomicAdd(&g_sum[lane * 4 + 1], (double)t1);
        atomicAdd(&g_sum[lane * 4 + 2], (double)t2);
        atomicAdd(&g_sum[lane * 4 + 3], (double)t3);
    }
    __syncthreads();
    sh[tid][0] = q0; sh[tid][1] = q1; sh[tid][2] = q2; sh[tid][3] = q3;
    __syncthreads();
    if (rg == 0) {
        float t0 = 0.f, t1 = 0.f, t2 = 0.f, t3 = 0.f;
#pragma unroll
        for (int g = 0; g < 8; g++) {
            t0 += sh[g * 32 + lane][0];
            t1 += sh[g * 32 + lane][1];
            t2 += sh[g * 32 + lane][2];
            t3 += sh[g * 32 + lane][3];
        }
        atomicAdd(&g_sq[lane * 4 + 0], (double)t0);
        atomicAdd(&g_sq[lane * 4 + 1], (double)t1);
        atomicAdd(&g_sq[lane * 4 + 2], (double)t2);
        atomicAdd(&g_sq[lane * 4 + 3], (double)t3);
    }
}

__global__ void k_bn_prep(const float* __restrict__ gammal,
                          const float* __restrict__ betal) {
    int c = threadIdx.x;
    double mean = g_sum[c] / (double)NN;
    double var = g_sq[c] / (double)NN - mean * mean;
    if (var < 0.0) var = 0.0;
    float inv = rsqrtf((float)var + BN_EPS);
    float sc = gammal[c] * inv;
    g_scale[c] = sc;
    g_shift[c] = betal[c] - (float)mean * sc;
}

__global__ void k_bn_apply(float* __restrict__ out, int do_relu) {
    int idx = blockIdx.x * blockDim.x + threadIdx.x;  // over NN*32 float4s
    int lane = idx & 31;
    float4 x = ((const float4*)g_agg)[idx];
    float4 sc = ((const float4*)g_scale)[lane];
    float4 sf = ((const float4*)g_shift)[lane];
    float4 v;
    v.x = fmaf(x.x, sc.x, sf.x);
    v.y = fmaf(x.y, sc.y, sf.y);
    v.z = fmaf(x.z, sc.z, sf.z);
    v.w = fmaf(x.w, sc.w, sf.w);
    if (do_relu) {
        v.x = fmaxf(v.x, 0.f); v.y = fmaxf(v.y, 0.f);
        v.z = fmaxf(v.z, 0.f); v.w = fmaxf(v.w, 0.f);
    }
    ((float4*)g_h)[idx] = v;
    float4 t = ((float4*)out)[idx];
    t.x += v.x; t.y += v.y; t.z += v.z; t.w += v.w;
    ((float4*)out)[idx] = t;
}

// ---------------- launch ----------------
extern "C" void kernel_launch(void* const* d_in, const int* in_sizes, int n_in,
                              void* d_out, int out_size) {
    const int*   x     = (const int*)d_in[0];
    const int*   ei    = (const int*)d_in[1];
    const int*   attr  = (const int*)d_in[2];
    const float* at    = (const float*)d_in[3];
    const float* bt    = (const float*)d_in[4];
    const float* W     = (const float*)d_in[5];
    const float* b     = (const float*)d_in[6];
    const float* root  = (const float*)d_in[7];
    const float* gamma = (const float*)d_in[8];
    const float* beta  = (const float*)d_in[9];
    float* out = (float*)d_out;

    cudaFuncSetAttribute(k_gemm, cudaFuncAttributeMaxDynamicSharedMemorySize, GEMM_SMEM);

    k_node_enc<<<NN / 8, 256>>>(x, at, out);
    k_deg_init<<<(NN + 255) / 256, 256>>>();
    k_deg_count<<<(EE + 255) / 256, 256>>>(ei);
    k_dis<<<(NN + 255) / 256, 256>>>();
    k_edge_enc<<<EE / 8, 256>>>(ei, attr, bt);

    for (int l = 0; l < LL; l++) {
        k_gemm<<<NN / 64, 256, GEMM_SMEM>>>(W + (size_t)l * DD * DD,
                                            b + (size_t)l * DD,
                                            root + (size_t)l * DD);
        k_msg<<<EE / 8, 256>>>(ei);
        k_stats<<<STATS_BLOCKS, 256>>>();
        k_bn_prep<<<1, 128>>>(gamma + (size_t)l * DD, beta + (size_t)l * DD);
        k_bn_apply<<<NN * 32 / 256, 256>>>(out, l < LL - 1 ? 1 : 0);
    }
}

// round 4
// speedup vs baseline: 1.4821x; 1.1049x over previous
#include <cuda_runtime.h>

#define NN 200000
#define EE 400000
#define DD 128
#define LL 5
#define BN_EPS 1e-5f

#define AS 132                         // padded smem stride (words)
#define GEMM_SMEM ((64 * AS + 128 * AS) * 4)
#define STATS_BLOCKS 1184
#define SCAN_BLK 512
#define SCAN_NBLK ((NN + SCAN_BLK - 1) / SCAN_BLK)   // 391

// ---------------- scratch (static device globals; no allocation) ----------------
__device__ float g_h[(size_t)NN * DD];      // h0 (layer-0 input)
__device__ float g_hl[(size_t)NN * DD];     // linear output
__device__ float g_agg[(size_t)NN * DD];    // self-term + scatter accum (pre-BN out)
__device__ float g_hbuf[(size_t)4 * NN * DD]; // post-BN h1..h4 for final total
__device__ float g_ee[(size_t)EE * DD];     // edge embeddings (sorted order)
__device__ float g_norm[EE];                // sorted
__device__ int   g_rows[EE];                // sorted src
__device__ int   g_cols[EE];                // sorted dst
__device__ int   g_perm[EE];
__device__ int   g_cnt[NN];
__device__ int   g_off[NN];
__device__ int   g_cursor[NN];
__device__ int   g_bsum[SCAN_BLK];
__device__ float g_deg[NN];
__device__ float g_dis[NN];
__device__ float g_invdeg[NN];
__device__ double g_sum[DD];
__device__ double g_sq[DD];
__device__ float g_scale[DD];
__device__ float g_shift[DD];

// ---------------- encoders / setup ----------------
__global__ void k_node_enc(const int* __restrict__ x,
                           const float* __restrict__ at,
                           float* __restrict__ out) {
    int node = blockIdx.x * 8 + (threadIdx.x >> 5);
    if (node >= NN) return;
    int lane = threadIdx.x & 31;
    float4 acc = make_float4(0.f, 0.f, 0.f, 0.f);
#pragma unroll
    for (int c = 0; c < 9; c++) {
        int idx = x[node * 9 + c];
        const float4* t = (const float4*)(at + ((size_t)c * 100 + idx) * DD);
        float4 v = t[lane];
        acc.x += v.x; acc.y += v.y; acc.z += v.z; acc.w += v.w;
    }
    size_t o = (size_t)node * 32 + lane;
    ((float4*)g_h)[o] = acc;
    ((float4*)out)[o] = acc;
}

__global__ void k_deg_init() {
    int i = blockIdx.x * blockDim.x + threadIdx.x;
    if (i < NN) { g_deg[i] = 1.0f; g_cnt[i] = 0; }
}

__global__ void k_deg_count(const int* __restrict__ ei) {
    int e = blockIdx.x * blockDim.x + threadIdx.x;
    if (e < EE) {
        atomicAdd(&g_deg[ei[e]], 1.0f);        // by source (degree)
        atomicAdd(&g_cnt[ei[EE + e]], 1);      // by dest (sort histogram)
    }
}

__global__ void k_dis() {
    int i = blockIdx.x * blockDim.x + threadIdx.x;
    if (i < NN) {
        float d = g_deg[i];
        g_dis[i] = rsqrtf(d);
        g_invdeg[i] = 1.0f / d;
    }
}

// ---- 2-level exclusive scan of g_cnt -> g_off ----
__global__ void k_scan1() {
    __shared__ int sh[SCAN_BLK];
    int tid = threadIdx.x;
    int i = blockIdx.x * SCAN_BLK + tid;
    int v = (i < NN) ? g_cnt[i] : 0;
    sh[tid] = v;
    __syncthreads();
#pragma unroll
    for (int s = 1; s < SCAN_BLK; s <<= 1) {
        int t = (tid >= s) ? sh[tid - s] : 0;
        __syncthreads();
        sh[tid] += t;
        __syncthreads();
    }
    if (i < NN) g_off[i] = sh[tid] - v;      // exclusive
    if (tid == SCAN_BLK - 1) g_bsum[blockIdx.x] = sh[tid];
}

__global__ void k_scan2() {
    __shared__ int sh[SCAN_BLK];
    int tid = threadIdx.x;
    int v = (tid < SCAN_NBLK) ? g_bsum[tid] : 0;
    sh[tid] = v;
    __syncthreads();
#pragma unroll
    for (int s = 1; s < SCAN_BLK; s <<= 1) {
        int t = (tid >= s) ? sh[tid - s] : 0;
        __syncthreads();
        sh[tid] += t;
        __syncthreads();
    }
    if (tid < SCAN_NBLK) g_bsum[tid] = sh[tid] - v;   // exclusive block offsets
}

__global__ void k_scan3() {
    int i = blockIdx.x * blockDim.x + threadIdx.x;
    if (i < NN) {
        int o = g_off[i] + g_bsum[i / SCAN_BLK];
        g_off[i] = o;
        g_cursor[i] = o;
    }
}

__global__ void k_scatter(const int* __restrict__ ei) {
    int e = blockIdx.x * blockDim.x + threadIdx.x;
    if (e < EE) {
        int c = ei[EE + e];
        int pos = atomicAdd(&g_cursor[c], 1);
        g_perm[pos] = e;
    }
}

// edge embedding + norm + row/col, in sorted order
__global__ void k_edge_enc(const int* __restrict__ ei,
                           const int* __restrict__ attr,
                           const float* __restrict__ bt) {
    int p = blockIdx.x * 8 + (threadIdx.x >> 5);
    if (p >= EE) return;
    int lane = threadIdx.x & 31;
    int e = g_perm[p];
    int r = ei[e], c = ei[EE + e];
    float4 acc = make_float4(0.f, 0.f, 0.f, 0.f);
#pragma unroll
    for (int cc = 0; cc < 3; cc++) {
        int idx = attr[e * 3 + cc];
        const float4* t = (const float4*)(bt + ((size_t)cc * 10 + idx) * DD);
        float4 v = t[lane];
        acc.x += v.x; acc.y += v.y; acc.z += v.z; acc.w += v.w;
    }
    ((float4*)g_ee)[(size_t)p * 32 + lane] = acc;
    if (lane == 0) {
        g_rows[p] = r;
        g_cols[p] = c;
        g_norm[p] = g_dis[r] * g_dis[c];
    }
}

// ---------------- GEMM (tf32 mma.sync) with fused BN-in / combine-out ----------------
// MODE 0: in = g_h (raw).  MODE 1: in = bn_relu(g_agg) (in-place safe), also written to hbuf.
// out: hl = in @ W^T + b ; agg = relu(hl + root) * invdeg
template <int MODE>
__global__ __launch_bounds__(256, 2)
void k_gemm(const float* __restrict__ Wl, const float* __restrict__ bl,
            const float* __restrict__ rootl, float* __restrict__ hbuf) {
    extern __shared__ unsigned smem_u[];
    unsigned* As = smem_u;             // [64][AS]
    unsigned* Bs = smem_u + 64 * AS;   // [128][AS]
    int tid = threadIdx.x;
    int row0 = blockIdx.x * 64;        // NN = 64 * 3125 exactly

    if (blockIdx.x == 0 && tid < DD) { g_sum[tid] = 0.0; g_sq[tid] = 0.0; }

    // stage A rows (apply BN+relu for MODE 1), fp32 -> tf32
    const float4* src4 = (const float4*)(MODE ? g_agg : g_h) + (size_t)row0 * 32;
    for (int i = tid; i < 64 * 32; i += 256) {
        int r = i >> 5, c4 = i & 31;
        float4 v = src4[(size_t)r * 32 + c4];
        if (MODE) {
            float4 sc = ((const float4*)g_scale)[c4];
            float4 sf = ((const float4*)g_shift)[c4];
            v.x = fmaxf(fmaf(v.x, sc.x, sf.x), 0.f);
            v.y = fmaxf(fmaf(v.y, sc.y, sf.y), 0.f);
            v.z = fmaxf(fmaf(v.z, sc.z, sf.z), 0.f);
            v.w = fmaxf(fmaf(v.w, sc.w, sf.w), 0.f);
            ((float4*)hbuf)[(size_t)(row0 + r) * 32 + c4] = v;
        }
        unsigned u0, u1, u2, u3;
        asm("cvt.rna.tf32.f32 %0, %1;" : "=r"(u0) : "f"(v.x));
        asm("cvt.rna.tf32.f32 %0, %1;" : "=r"(u1) : "f"(v.y));
        asm("cvt.rna.tf32.f32 %0, %1;" : "=r"(u2) : "f"(v.z));
        asm("cvt.rna.tf32.f32 %0, %1;" : "=r"(u3) : "f"(v.w));
        *(uint4*)&As[r * AS + c4 * 4] = make_uint4(u0, u1, u2, u3);
    }
    // stage B (W rows)
    const float4* Wg4 = (const float4*)Wl;
    for (int i = tid; i < 128 * 32; i += 256) {
        int c4 = i & 31;
        float4 v = Wg4[i];
        unsigned u0, u1, u2, u3;
        asm("cvt.rna.tf32.f32 %0, %1;" : "=r"(u0) : "f"(v.x));
        asm("cvt.rna.tf32.f32 %0, %1;" : "=r"(u1) : "f"(v.y));
        asm("cvt.rna.tf32.f32 %0, %1;" : "=r"(u2) : "f"(v.z));
        asm("cvt.rna.tf32.f32 %0, %1;" : "=r"(u3) : "f"(v.w));
        *(uint4*)&Bs[(i >> 5) * AS + c4 * 4] = make_uint4(u0, u1, u2, u3);
    }
    __syncthreads();

    int w = tid >> 5, lane = tid & 31;
    int g = lane >> 2, tig = lane & 3;
    int rbase = (w & 3) * 16;
    int cbase = (w >> 2) * 64;

    float acc[8][4];
#pragma unroll
    for (int j = 0; j < 8; j++)
#pragma unroll
        for (int q = 0; q < 4; q++) acc[j][q] = 0.f;

#pragma unroll
    for (int ks = 0; ks < 16; ks++) {
        int k0 = ks * 8;
        unsigned a0 = As[(rbase + g) * AS + k0 + tig];
        unsigned a1 = As[(rbase + g + 8) * AS + k0 + tig];
        unsigned a2 = As[(rbase + g) * AS + k0 + tig + 4];
        unsigned a3 = As[(rbase + g + 8) * AS + k0 + tig + 4];
#pragma unroll
        for (int j = 0; j < 8; j++) {
            unsigned b0 = Bs[(cbase + j * 8 + g) * AS + k0 + tig];
            unsigned b1 = Bs[(cbase + j * 8 + g) * AS + k0 + tig + 4];
            asm("mma.sync.aligned.m16n8k8.row.col.f32.tf32.tf32.f32 "
                "{%0,%1,%2,%3},{%4,%5,%6,%7},{%8,%9},{%0,%1,%2,%3};"
                : "+f"(acc[j][0]), "+f"(acc[j][1]), "+f"(acc[j][2]), "+f"(acc[j][3])
                : "r"(a0), "r"(a1), "r"(a2), "r"(a3), "r"(b0), "r"(b1));
        }
    }

    int r0g = row0 + rbase + g;
    int r1g = r0g + 8;
    float id0 = g_invdeg[r0g];
    float id1 = g_invdeg[r1g];
#pragma unroll
    for (int j = 0; j < 8; j++) {
        int c0 = cbase + j * 8 + tig * 2;
        float bb0 = bl[c0], bb1 = bl[c0 + 1];
        float rr0 = rootl[c0], rr1 = rootl[c0 + 1];
        float h00 = acc[j][0] + bb0, h01 = acc[j][1] + bb1;
        float h10 = acc[j][2] + bb0, h11 = acc[j][3] + bb1;
        *(float2*)&g_hl[(size_t)r0g * DD + c0] = make_float2(h00, h01);
        *(float2*)&g_hl[(size_t)r1g * DD + c0] = make_float2(h10, h11);
        *(float2*)&g_agg[(size_t)r0g * DD + c0] =
            make_float2(fmaxf(h00 + rr0, 0.f) * id0, fmaxf(h01 + rr1, 0.f) * id0);
        *(float2*)&g_agg[(size_t)r1g * DD + c0] =
            make_float2(fmaxf(h10 + rr0, 0.f) * id1, fmaxf(h11 + rr1, 0.f) * id1);
    }
}

// ---------------- message: agg[col] += norm * relu(hl[row] + ee), sorted by col ----------------
__global__ void k_msg() {
    int p = blockIdx.x * 8 + (threadIdx.x >> 5);
    if (p >= EE) return;
    int lane = threadIdx.x & 31;
    int r = g_rows[p];
    int c = g_cols[p];
    float nrm = g_norm[p];
    float4 h = ((const float4*)g_hl)[(size_t)r * 32 + lane];
    float4 em = ((const float4*)g_ee)[(size_t)p * 32 + lane];
    float mx = nrm * fmaxf(h.x + em.x, 0.f);
    float my = nrm * fmaxf(h.y + em.y, 0.f);
    float mz = nrm * fmaxf(h.z + em.z, 0.f);
    float mw = nrm * fmaxf(h.w + em.w, 0.f);
    float* dst = g_agg + (size_t)c * DD + lane * 4;
    asm volatile("red.global.add.v4.f32 [%0], {%1, %2, %3, %4};"
                 :: "l"(dst), "f"(mx), "f"(my), "f"(mz), "f"(mw) : "memory");
}

// ---------------- BN statistics over g_agg ----------------
__global__ void k_stats() {
    int tid = threadIdx.x;
    int lane = tid & 31;
    int rg = tid >> 5;
    float s0 = 0.f, s1 = 0.f, s2 = 0.f, s3 = 0.f;
    float q0 = 0.f, q1 = 0.f, q2 = 0.f, q3 = 0.f;
    const float4* agg4 = (const float4*)g_agg;
    for (int n = blockIdx.x * 8 + rg; n < NN; n += gridDim.x * 8) {
        float4 o = agg4[(size_t)n * 32 + lane];
        s0 += o.x; s1 += o.y; s2 += o.z; s3 += o.w;
        q0 += o.x * o.x; q1 += o.y * o.y; q2 += o.z * o.z; q3 += o.w * o.w;
    }
    __shared__ float sh[256][4];
    sh[tid][0] = s0; sh[tid][1] = s1; sh[tid][2] = s2; sh[tid][3] = s3;
    __syncthreads();
    if (rg == 0) {
        float t0 = 0.f, t1 = 0.f, t2 = 0.f, t3 = 0.f;
#pragma unroll
        for (int g = 0; g < 8; g++) {
            t0 += sh[g * 32 + lane][0];
            t1 += sh[g * 32 + lane][1];
            t2 += sh[g * 32 + lane][2];
            t3 += sh[g * 32 + lane][3];
        }
        atomicAdd(&g_sum[lane * 4 + 0], (double)t0);
        atomicAdd(&g_sum[lane * 4 + 1], (double)t1);
        atomicAdd(&g_sum[lane * 4 + 2], (double)t2);
        atomicAdd(&g_sum[lane * 4 + 3], (double)t3);
    }
    __syncthreads();
    sh[tid][0] = q0; sh[tid][1] = q1; sh[tid][2] = q2; sh[tid][3] = q3;
    __syncthreads();
    if (rg == 0) {
        float t0 = 0.f, t1 = 0.f, t2 = 0.f, t3 = 0.f;
#pragma unroll
        for (int g = 0; g < 8; g++) {
            t0 += sh[g * 32 + lane][0];
            t1 += sh[g * 32 + lane][1];
            t2 += sh[g * 32 + lane][2];
            t3 += sh[g * 32 + lane][3];
        }
        atomicAdd(&g_sq[lane * 4 + 0], (double)t0);
        atomicAdd(&g_sq[lane * 4 + 1], (double)t1);
        atomicAdd(&g_sq[lane * 4 + 2], (double)t2);
        atomicAdd(&g_sq[lane * 4 + 3], (double)t3);
    }
}

__global__ void k_bn_prep(const float* __restrict__ gammal,
                          const float* __restrict__ betal) {
    int c = threadIdx.x;
    double mean = g_sum[c] / (double)NN;
    double var = g_sq[c] / (double)NN - mean * mean;
    if (var < 0.0) var = 0.0;
    float inv = rsqrtf((float)var + BN_EPS);
    float sc = gammal[c] * inv;
    g_scale[c] = sc;
    g_shift[c] = betal[c] - (float)mean * sc;
}

// final: out += h1..h4 + bn(agg_last) (no relu)
__global__ void k_total(float* __restrict__ out) {
    size_t idx = (size_t)blockIdx.x * blockDim.x + threadIdx.x;  // NN*32 float4s
    int lane = idx & 31;
    float4 a = ((const float4*)g_agg)[idx];
    float4 sc = ((const float4*)g_scale)[lane];
    float4 sf = ((const float4*)g_shift)[lane];
    float4 t = ((const float4*)out)[idx];
    t.x += fmaf(a.x, sc.x, sf.x);
    t.y += fmaf(a.y, sc.y, sf.y);
    t.z += fmaf(a.z, sc.z, sf.z);
    t.w += fmaf(a.w, sc.w, sf.w);
    const float4* hb = (const float4*)g_hbuf;
    size_t stride = (size_t)NN * 32;
#pragma unroll
    for (int l = 0; l < 4; l++) {
        float4 v = hb[idx + stride * l];
        t.x += v.x; t.y += v.y; t.z += v.z; t.w += v.w;
    }
    ((float4*)out)[idx] = t;
}

// ---------------- launch ----------------
extern "C" void kernel_launch(void* const* d_in, const int* in_sizes, int n_in,
                              void* d_out, int out_size) {
    const int*   x     = (const int*)d_in[0];
    const int*   ei    = (const int*)d_in[1];
    const int*   attr  = (const int*)d_in[2];
    const float* at    = (const float*)d_in[3];
    const float* bt    = (const float*)d_in[4];
    const float* W     = (const float*)d_in[5];
    const float* b     = (const float*)d_in[6];
    const float* root  = (const float*)d_in[7];
    const float* gamma = (const float*)d_in[8];
    const float* beta  = (const float*)d_in[9];
    float* out = (float*)d_out;

    cudaFuncSetAttribute(k_gemm<0>, cudaFuncAttributeMaxDynamicSharedMemorySize, GEMM_SMEM);
    cudaFuncSetAttribute(k_gemm<1>, cudaFuncAttributeMaxDynamicSharedMemorySize, GEMM_SMEM);

    k_node_enc<<<NN / 8, 256>>>(x, at, out);
    k_deg_init<<<(NN + 255) / 256, 256>>>();
    k_deg_count<<<(EE + 255) / 256, 256>>>(ei);
    k_dis<<<(NN + 255) / 256, 256>>>();
    k_scan1<<<SCAN_NBLK, SCAN_BLK>>>();
    k_scan2<<<1, SCAN_BLK>>>();
    k_scan3<<<(NN + 255) / 256, 256>>>();
    k_scatter<<<(EE + 255) / 256, 256>>>(ei);
    k_edge_enc<<<EE / 8, 256>>>(ei, attr, bt);

    float* hbuf = (float*)nullptr;
    for (int l = 0; l < LL; l++) {
        const float* Wl = W + (size_t)l * DD * DD;
        const float* bl = b + (size_t)l * DD;
        const float* rl = root + (size_t)l * DD;
        if (l == 0) {
            k_gemm<0><<<NN / 64, 256, GEMM_SMEM>>>(Wl, bl, rl, nullptr);
        } else {
            cudaGetSymbolAddress((void**)&hbuf, g_hbuf);
            k_gemm<1><<<NN / 64, 256, GEMM_SMEM>>>(Wl, bl, rl,
                                                   hbuf + (size_t)(l - 1) * NN * DD);
        }
        k_msg<<<EE / 8, 256>>>();
        k_stats<<<STATS_BLOCKS, 256>>>();
        k_bn_prep<<<1, 128>>>(gamma + (size_t)l * DD, beta + (size_t)l * DD);
    }
    k_total<<<NN * 32 / 256, 256>>>(out);
}

// round 6
// speedup vs baseline: 1.6359x; 1.1038x over previous
#include <cuda_runtime.h>

#define NN 200000
#define EE 400000
#define DD 128
#define LL 5
#define BN_EPS 1e-5f

#define AS 132                         // padded smem stride (words)
#define GEMM_SMEM ((64 * AS + 128 * AS) * 4)
#define MSG_BLOCKS 1184
#define SCAN_BLK 512
#define SCAN_NBLK ((NN + SCAN_BLK - 1) / SCAN_BLK)   // 391

// ---------------- scratch (static device globals; no allocation) ----------------
__device__ float g_h[(size_t)NN * DD];      // h0 (layer-0 input)
__device__ float g_hl[(size_t)NN * DD];     // linear output
__device__ float g_agg[(size_t)NN * DD];    // pre-BN layer output
__device__ float g_hbuf[(size_t)4 * NN * DD]; // post-BN h1..h4 for final total
__device__ float g_ee[(size_t)EE * DD];     // edge embeddings (dest-sorted order)
__device__ float g_norm[EE];                // dest-sorted
__device__ int   g_rows[EE];                // dest-sorted src
__device__ int   g_perm[EE];
__device__ int   g_cnt[NN];
__device__ int   g_off[NN + 1];
__device__ int   g_cursor[NN];
__device__ int   g_bsum[SCAN_BLK];
__device__ float g_deg[NN];
__device__ float g_dis[NN];
__device__ float g_invdeg[NN];
__device__ double g_sum[DD];
__device__ double g_sq[DD];
__device__ float g_scale[DD];
__device__ float g_shift[DD];

// ---------------- encoders / setup ----------------
__global__ void k_node_enc(const int* __restrict__ x,
                           const float* __restrict__ at,
                           float* __restrict__ out) {
    int node = blockIdx.x * 8 + (threadIdx.x >> 5);
    if (node >= NN) return;
    int lane = threadIdx.x & 31;
    float4 acc = make_float4(0.f, 0.f, 0.f, 0.f);
#pragma unroll
    for (int c = 0; c < 9; c++) {
        int idx = x[node * 9 + c];
        const float4* t = (const float4*)(at + ((size_t)c * 100 + idx) * DD);
        float4 v = t[lane];
        acc.x += v.x; acc.y += v.y; acc.z += v.z; acc.w += v.w;
    }
    size_t o = (size_t)node * 32 + lane;
    ((float4*)g_h)[o] = acc;
    ((float4*)out)[o] = acc;
}

__global__ void k_deg_init() {
    int i = blockIdx.x * blockDim.x + threadIdx.x;
    if (i < NN) { g_deg[i] = 1.0f; g_cnt[i] = 0; }
}

__global__ void k_deg_count(const int* __restrict__ ei) {
    int e = blockIdx.x * blockDim.x + threadIdx.x;
    if (e < EE) {
        atomicAdd(&g_deg[ei[e]], 1.0f);        // by source (degree)
        atomicAdd(&g_cnt[ei[EE + e]], 1);      // by dest (sort histogram)
    }
}

__global__ void k_dis() {
    int i = blockIdx.x * blockDim.x + threadIdx.x;
    if (i < NN) {
        float d = g_deg[i];
        g_dis[i] = rsqrtf(d);
        g_invdeg[i] = 1.0f / d;
    }
}

// ---- 2-level exclusive scan of g_cnt -> g_off ----
__global__ void k_scan1() {
    __shared__ int sh[SCAN_BLK];
    int tid = threadIdx.x;
    int i = blockIdx.x * SCAN_BLK + tid;
    int v = (i < NN) ? g_cnt[i] : 0;
    sh[tid] = v;
    __syncthreads();
#pragma unroll
    for (int s = 1; s < SCAN_BLK; s <<= 1) {
        int t = (tid >= s) ? sh[tid - s] : 0;
        __syncthreads();
        sh[tid] += t;
        __syncthreads();
    }
    if (i < NN) g_off[i] = sh[tid] - v;      // exclusive
    if (tid == SCAN_BLK - 1) g_bsum[blockIdx.x] = sh[tid];
}

__global__ void k_scan2() {
    __shared__ int sh[SCAN_BLK];
    int tid = threadIdx.x;
    int v = (tid < SCAN_NBLK) ? g_bsum[tid] : 0;
    sh[tid] = v;
    __syncthreads();
#pragma unroll
    for (int s = 1; s < SCAN_BLK; s <<= 1) {
        int t = (tid >= s) ? sh[tid - s] : 0;
        __syncthreads();
        sh[tid] += t;
        __syncthreads();
    }
    if (tid < SCAN_NBLK) g_bsum[tid] = sh[tid] - v;   // exclusive block offsets
}

__global__ void k_scan3() {
    int i = blockIdx.x * blockDim.x + threadIdx.x;
    if (i < NN) {
        int o = g_off[i] + g_bsum[i / SCAN_BLK];
        g_off[i] = o;
        g_cursor[i] = o;
    }
    if (i == 0) g_off[NN] = EE;
}

__global__ void k_scatter(const int* __restrict__ ei) {
    int e = blockIdx.x * blockDim.x + threadIdx.x;
    if (e < EE) {
        int c = ei[EE + e];
        int pos = atomicAdd(&g_cursor[c], 1);
        g_perm[pos] = e;
    }
}

// edge embedding + norm + row, in dest-sorted order
__global__ void k_edge_enc(const int* __restrict__ ei,
                           const int* __restrict__ attr,
                           const float* __restrict__ bt) {
    int p = blockIdx.x * 8 + (threadIdx.x >> 5);
    if (p >= EE) return;
    int lane = threadIdx.x & 31;
    int e = g_perm[p];
    int r = ei[e], c = ei[EE + e];
    float4 acc = make_float4(0.f, 0.f, 0.f, 0.f);
#pragma unroll
    for (int cc = 0; cc < 3; cc++) {
        int idx = attr[e * 3 + cc];
        const float4* t = (const float4*)(bt + ((size_t)cc * 10 + idx) * DD);
        float4 v = t[lane];
        acc.x += v.x; acc.y += v.y; acc.z += v.z; acc.w += v.w;
    }
    ((float4*)g_ee)[(size_t)p * 32 + lane] = acc;
    if (lane == 0) {
        g_rows[p] = r;
        g_norm[p] = g_dis[r] * g_dis[c];
    }
}

// ---------------- GEMM (tf32 mma.sync) with fused BN-in ----------------
// MODE 0: in = g_h (raw).  MODE 1: in = bn_relu(g_agg) (in-place safe), also -> hbuf.
// out: hl = in @ W^T + b
template <int MODE>
__global__ __launch_bounds__(256, 2)
void k_gemm(const float* __restrict__ Wl, const float* __restrict__ bl,
            float* __restrict__ hbuf) {
    extern __shared__ unsigned smem_u[];
    unsigned* As = smem_u;             // [64][AS]
    unsigned* Bs = smem_u + 64 * AS;   // [128][AS]
    int tid = threadIdx.x;
    int row0 = blockIdx.x * 64;        // NN = 64 * 3125 exactly

    if (blockIdx.x == 0 && tid < DD) { g_sum[tid] = 0.0; g_sq[tid] = 0.0; }

    const float4* src4 = (const float4*)(MODE ? g_agg : g_h) + (size_t)row0 * 32;
    for (int i = tid; i < 64 * 32; i += 256) {
        int r = i >> 5, c4 = i & 31;
        float4 v = src4[(size_t)r * 32 + c4];
        if (MODE) {
            float4 sc = ((const float4*)g_scale)[c4];
            float4 sf = ((const float4*)g_shift)[c4];
            v.x = fmaxf(fmaf(v.x, sc.x, sf.x), 0.f);
            v.y = fmaxf(fmaf(v.y, sc.y, sf.y), 0.f);
            v.z = fmaxf(fmaf(v.z, sc.z, sf.z), 0.f);
            v.w = fmaxf(fmaf(v.w, sc.w, sf.w), 0.f);
            ((float4*)hbuf)[(size_t)(row0 + r) * 32 + c4] = v;
        }
        unsigned u0, u1, u2, u3;
        asm("cvt.rna.tf32.f32 %0, %1;" : "=r"(u0) : "f"(v.x));
        asm("cvt.rna.tf32.f32 %0, %1;" : "=r"(u1) : "f"(v.y));
        asm("cvt.rna.tf32.f32 %0, %1;" : "=r"(u2) : "f"(v.z));
        asm("cvt.rna.tf32.f32 %0, %1;" : "=r"(u3) : "f"(v.w));
        *(uint4*)&As[r * AS + c4 * 4] = make_uint4(u0, u1, u2, u3);
    }
    const float4* Wg4 = (const float4*)Wl;
    for (int i = tid; i < 128 * 32; i += 256) {
        int c4 = i & 31;
        float4 v = Wg4[i];
        unsigned u0, u1, u2, u3;
        asm("cvt.rna.tf32.f32 %0, %1;" : "=r"(u0) : "f"(v.x));
        asm("cvt.rna.tf32.f32 %0, %1;" : "=r"(u1) : "f"(v.y));
        asm("cvt.rna.tf32.f32 %0, %1;" : "=r"(u2) : "f"(v.z));
        asm("cvt.rna.tf32.f32 %0, %1;" : "=r"(u3) : "f"(v.w));
        *(uint4*)&Bs[(i >> 5) * AS + c4 * 4] = make_uint4(u0, u1, u2, u3);
    }
    __syncthreads();

    int w = tid >> 5, lane = tid & 31;
    int g = lane >> 2, tig = lane & 3;
    int rbase = (w & 3) * 16;
    int cbase = (w >> 2) * 64;

    float acc[8][4];
#pragma unroll
    for (int j = 0; j < 8; j++)
#pragma unroll
        for (int q = 0; q < 4; q++) acc[j][q] = 0.f;

#pragma unroll
    for (int ks = 0; ks < 16; ks++) {
        int k0 = ks * 8;
        unsigned a0 = As[(rbase + g) * AS + k0 + tig];
        unsigned a1 = As[(rbase + g + 8) * AS + k0 + tig];
        unsigned a2 = As[(rbase + g) * AS + k0 + tig + 4];
        unsigned a3 = As[(rbase + g + 8) * AS + k0 + tig + 4];
#pragma unroll
        for (int j = 0; j < 8; j++) {
            unsigned b0 = Bs[(cbase + j * 8 + g) * AS + k0 + tig];
            unsigned b1 = Bs[(cbase + j * 8 + g) * AS + k0 + tig + 4];
            asm("mma.sync.aligned.m16n8k8.row.col.f32.tf32.tf32.f32 "
                "{%0,%1,%2,%3},{%4,%5,%6,%7},{%8,%9},{%0,%1,%2,%3};"
                : "+f"(acc[j][0]), "+f"(acc[j][1]), "+f"(acc[j][2]), "+f"(acc[j][3])
                : "r"(a0), "r"(a1), "r"(a2), "r"(a3), "r"(b0), "r"(b1));
        }
    }

    int r0g = row0 + rbase + g;
    int r1g = r0g + 8;
#pragma unroll
    for (int j = 0; j < 8; j++) {
        int c0 = cbase + j * 8 + tig * 2;
        float bb0 = bl[c0], bb1 = bl[c0 + 1];
        *(float2*)&g_hl[(size_t)r0g * DD + c0] =
            make_float2(acc[j][0] + bb0, acc[j][1] + bb1);
        *(float2*)&g_hl[(size_t)r1g * DD + c0] =
            make_float2(acc[j][2] + bb0, acc[j][3] + bb1);
    }
}

// ---------------- fused: aggregate (CSR by dest, no atomics) + BN stats ----------------
// agg[c] = relu(hl[c]+root)*invdeg + sum_{p in [off[c],off[c+1])} norm[p]*relu(hl[rows[p]]+ee[p])
__global__ void k_msg_fused(const float* __restrict__ rootl) {
    int tid = threadIdx.x;
    int lane = tid & 31;
    int wraw = tid >> 5;
    int gw = blockIdx.x * 8 + wraw;
    const int TOTW = MSG_BLOCKS * 8;
    const int chunk = (NN + TOTW - 1) / TOTW;
    int c0 = gw * chunk;
    int c1 = c0 + chunk; if (c1 > NN) c1 = NN;

    float4 r4 = ((const float4*)rootl)[lane];
    float s0 = 0.f, s1 = 0.f, s2 = 0.f, s3 = 0.f;
    float q0 = 0.f, q1 = 0.f, q2 = 0.f, q3 = 0.f;
    const float4* hl4 = (const float4*)g_hl;
    const float4* ee4 = (const float4*)g_ee;
    float4* agg4 = (float4*)g_agg;

    for (int c = c0; c < c1; c++) {
        float idg = g_invdeg[c];
        float4 h = hl4[(size_t)c * 32 + lane];
        float4 o;
        o.x = fmaxf(h.x + r4.x, 0.f) * idg;
        o.y = fmaxf(h.y + r4.y, 0.f) * idg;
        o.z = fmaxf(h.z + r4.z, 0.f) * idg;
        o.w = fmaxf(h.w + r4.w, 0.f) * idg;
        int e0 = g_off[c], e1 = g_off[c + 1];
        for (int p = e0; p < e1; p++) {
            int r = g_rows[p];
            float nrm = g_norm[p];
            float4 hh = hl4[(size_t)r * 32 + lane];
            float4 em = ee4[(size_t)p * 32 + lane];
            o.x = fmaf(nrm, fmaxf(hh.x + em.x, 0.f), o.x);
            o.y = fmaf(nrm, fmaxf(hh.y + em.y, 0.f), o.y);
            o.z = fmaf(nrm, fmaxf(hh.z + em.z, 0.f), o.z);
            o.w = fmaf(nrm, fmaxf(hh.w + em.w, 0.f), o.w);
        }
        agg4[(size_t)c * 32 + lane] = o;
        s0 += o.x; s1 += o.y; s2 += o.z; s3 += o.w;
        q0 += o.x * o.x; q1 += o.y * o.y; q2 += o.z * o.z; q3 += o.w * o.w;
    }

    __shared__ float sh[256][4];
    sh[tid][0] = s0; sh[tid][1] = s1; sh[tid][2] = s2; sh[tid][3] = s3;
    __syncthreads();
    if (wraw == 0) {
        float t0 = 0.f, t1 = 0.f, t2 = 0.f, t3 = 0.f;
#pragma unroll
        for (int g = 0; g < 8; g++) {
            t0 += sh[g * 32 + lane][0];
            t1 += sh[g * 32 + lane][1];
            t2 += sh[g * 32 + lane][2];
            t3 += sh[g * 32 + lane][3];
        }
        atomicAdd(&g_sum[lane * 4 + 0], (double)t0);
        atomicAdd(&g_sum[lane * 4 + 1], (double)t1);
        atomicAdd(&g_sum[lane * 4 + 2], (double)t2);
        atomicAdd(&g_sum[lane * 4 + 3], (double)t3);
    }
    __syncthreads();
    sh[tid][0] = q0; sh[tid][1] = q1; sh[tid][2] = q2; sh[tid][3] = q3;
    __syncthreads();
    if (wraw == 0) {
        float t0 = 0.f, t1 = 0.f, t2 = 0.f, t3 = 0.f;
#pragma unroll
        for (int g = 0; g < 8; g++) {
            t0 += sh[g * 32 + lane][0];
            t1 += sh[g * 32 + lane][1];
            t2 += sh[g * 32 + lane][2];
            t3 += sh[g * 32 + lane][3];
        }
        atomicAdd(&g_sq[lane * 4 + 0], (double)t0);
        atomicAdd(&g_sq[lane * 4 + 1], (double)t1);
        atomicAdd(&g_sq[lane * 4 + 2], (double)t2);
        atomicAdd(&g_sq[lane * 4 + 3], (double)t3);
    }
}

__global__ void k_bn_prep(const float* __restrict__ gammal,
                          const float* __restrict__ betal) {
    int c = threadIdx.x;
    double mean = g_sum[c] / (double)NN;
    double var = g_sq[c] / (double)NN - mean * mean;
    if (var < 0.0) var = 0.0;
    float inv = rsqrtf((float)var + BN_EPS);
    float sc = gammal[c] * inv;
    g_scale[c] = sc;
    g_shift[c] = betal[c] - (float)mean * sc;
}

// final: out += h1..h4 + bn(agg_last) (no relu)
__global__ void k_total(float* __restrict__ out) {
    size_t idx = (size_t)blockIdx.x * blockDim.x + threadIdx.x;  // NN*32 float4s
    int lane = idx & 31;
    float4 a = ((const float4*)g_agg)[idx];
    float4 sc = ((const float4*)g_scale)[lane];
    float4 sf = ((const float4*)g_shift)[lane];
    float4 t = ((const float4*)out)[idx];
    t.x += fmaf(a.x, sc.x, sf.x);
    t.y += fmaf(a.y, sc.y, sf.y);
    t.z += fmaf(a.z, sc.z, sf.z);
    t.w += fmaf(a.w, sc.w, sf.w);
    const float4* hb = (const float4*)g_hbuf;
    size_t stride = (size_t)NN * 32;
#pragma unroll
    for (int l = 0; l < 4; l++) {
        float4 v = hb[idx + stride * l];
        t.x += v.x; t.y += v.y; t.z += v.z; t.w += v.w;
    }
    ((float4*)out)[idx] = t;
}

// ---------------- launch ----------------
extern "C" void kernel_launch(void* const* d_in, const int* in_sizes, int n_in,
                              void* d_out, int out_size) {
    const int*   x     = (const int*)d_in[0];
    const int*   ei    = (const int*)d_in[1];
    const int*   attr  = (const int*)d_in[2];
    const float* at    = (const float*)d_in[3];
    const float* bt    = (const float*)d_in[4];
    const float* W     = (const float*)d_in[5];
    const float* b     = (const float*)d_in[6];
    const float* root  = (const float*)d_in[7];
    const float* gamma = (const float*)d_in[8];
    const float* beta  = (const float*)d_in[9];
    float* out = (float*)d_out;

    cudaFuncSetAttribute(k_gemm<0>, cudaFuncAttributeMaxDynamicSharedMemorySize, GEMM_SMEM);
    cudaFuncSetAttribute(k_gemm<1>, cudaFuncAttributeMaxDynamicSharedMemorySize, GEMM_SMEM);

    k_node_enc<<<NN / 8, 256>>>(x, at, out);
    k_deg_init<<<(NN + 255) / 256, 256>>>();
    k_deg_count<<<(EE + 255) / 256, 256>>>(ei);
    k_dis<<<(NN + 255) / 256, 256>>>();
    k_scan1<<<SCAN_NBLK, SCAN_BLK>>>();
    k_scan2<<<1, SCAN_BLK>>>();
    k_scan3<<<(NN + 255) / 256, 256>>>();
    k_scatter<<<(EE + 255) / 256, 256>>>(ei);
    k_edge_enc<<<EE / 8, 256>>>(ei, attr, bt);

    float* hbuf = (float*)nullptr;
    cudaGetSymbolAddress((void**)&hbuf, g_hbuf);
    for (int l = 0; l < LL; l++) {
        const float* Wl = W + (size_t)l * DD * DD;
        const float* bl = b + (size_t)l * DD;
        if (l == 0) {
            k_gemm<0><<<NN / 64, 256, GEMM_SMEM>>>(Wl, bl, nullptr);
        } else {
            k_gemm<1><<<NN / 64, 256, GEMM_SMEM>>>(Wl, bl,
                                                   hbuf + (size_t)(l - 1) * NN * DD);
        }
        k_msg_fused<<<MSG_BLOCKS, 256>>>(root + (size_t)l * DD);
        k_bn_prep<<<1, 128>>>(gamma + (size_t)l * DD, beta + (size_t)l * DD);
    }
    k_total<<<NN * 32 / 256, 256>>>(out);
}

// round 7
// speedup vs baseline: 1.7674x; 1.0803x over previous
#include <cuda_runtime.h>
#include <cuda_fp16.h>

#define NN 200000
#define EE 400000
#define DD 128
#define LL 5
#define BN_EPS 1e-5f

#define AS 132                         // padded smem stride (words)
#define GEMM_SMEM ((64 * AS + 128 * AS) * 4)
#define MSG_BLOCKS 1184
#define SCAN_BLK 512
#define SCAN_NBLK ((NN + SCAN_BLK - 1) / SCAN_BLK)   // 391

// ---------------- scratch (static device globals; no allocation) ----------------
__device__ float  g_h[(size_t)NN * DD];       // h0 (layer-0 input)
__device__ __half g_hl16[(size_t)NN * DD];    // linear output (fp16)
__device__ float  g_agg[(size_t)NN * DD];     // pre-BN layer output
__device__ float  g_hbuf[(size_t)4 * NN * DD]; // post-BN h1..h4 for final total
__device__ __half g_ee16[(size_t)EE * DD];    // edge embeddings (dest-sorted, fp16)
__device__ float  g_norm[EE];                 // dest-sorted
__device__ int    g_rows[EE];                 // dest-sorted src
__device__ int    g_perm[EE];
__device__ int    g_cnt[NN];
__device__ int    g_off[NN + 1];
__device__ int    g_cursor[NN];
__device__ int    g_bsum[SCAN_BLK];
__device__ float  g_deg[NN];
__device__ float  g_dis[NN];
__device__ float  g_invdeg[NN];
__device__ double g_sum[DD];
__device__ double g_sq[DD];
__device__ float  g_scale[DD];
__device__ float  g_shift[DD];

// ---------------- encoders / setup ----------------
__global__ void k_node_enc(const int* __restrict__ x,
                           const float* __restrict__ at,
                           float* __restrict__ out) {
    int node = blockIdx.x * 8 + (threadIdx.x >> 5);
    if (node >= NN) return;
    int lane = threadIdx.x & 31;
    float4 acc = make_float4(0.f, 0.f, 0.f, 0.f);
#pragma unroll
    for (int c = 0; c < 9; c++) {
        int idx = x[node * 9 + c];
        const float4* t = (const float4*)(at + ((size_t)c * 100 + idx) * DD);
        float4 v = t[lane];
        acc.x += v.x; acc.y += v.y; acc.z += v.z; acc.w += v.w;
    }
    size_t o = (size_t)node * 32 + lane;
    ((float4*)g_h)[o] = acc;
    ((float4*)out)[o] = acc;
}

__global__ void k_deg_init() {
    int i = blockIdx.x * blockDim.x + threadIdx.x;
    if (i < NN) { g_deg[i] = 1.0f; g_cnt[i] = 0; }
}

__global__ void k_deg_count(const int* __restrict__ ei) {
    int e = blockIdx.x * blockDim.x + threadIdx.x;
    if (e < EE) {
        atomicAdd(&g_deg[ei[e]], 1.0f);        // by source (degree)
        atomicAdd(&g_cnt[ei[EE + e]], 1);      // by dest (sort histogram)
    }
}

__global__ void k_dis() {
    int i = blockIdx.x * blockDim.x + threadIdx.x;
    if (i < NN) {
        float d = g_deg[i];
        g_dis[i] = rsqrtf(d);
        g_invdeg[i] = 1.0f / d;
    }
}

// ---- 2-level exclusive scan of g_cnt -> g_off ----
__global__ void k_scan1() {
    __shared__ int sh[SCAN_BLK];
    int tid = threadIdx.x;
    int i = blockIdx.x * SCAN_BLK + tid;
    int v = (i < NN) ? g_cnt[i] : 0;
    sh[tid] = v;
    __syncthreads();
#pragma unroll
    for (int s = 1; s < SCAN_BLK; s <<= 1) {
        int t = (tid >= s) ? sh[tid - s] : 0;
        __syncthreads();
        sh[tid] += t;
        __syncthreads();
    }
    if (i < NN) g_off[i] = sh[tid] - v;      // exclusive
    if (tid == SCAN_BLK - 1) g_bsum[blockIdx.x] = sh[tid];
}

__global__ void k_scan2() {
    __shared__ int sh[SCAN_BLK];
    int tid = threadIdx.x;
    int v = (tid < SCAN_NBLK) ? g_bsum[tid] : 0;
    sh[tid] = v;
    __syncthreads();
#pragma unroll
    for (int s = 1; s < SCAN_BLK; s <<= 1) {
        int t = (tid >= s) ? sh[tid - s] : 0;
        __syncthreads();
        sh[tid] += t;
        __syncthreads();
    }
    if (tid < SCAN_NBLK) g_bsum[tid] = sh[tid] - v;   // exclusive block offsets
}

__global__ void k_scan3() {
    int i = blockIdx.x * blockDim.x + threadIdx.x;
    if (i < NN) {
        int o = g_off[i] + g_bsum[i / SCAN_BLK];
        g_off[i] = o;
        g_cursor[i] = o;
    }
    if (i == 0) g_off[NN] = EE;
}

__global__ void k_scatter(const int* __restrict__ ei) {
    int e = blockIdx.x * blockDim.x + threadIdx.x;
    if (e < EE) {
        int c = ei[EE + e];
        int pos = atomicAdd(&g_cursor[c], 1);
        g_perm[pos] = e;
    }
}

// edge embedding (fp16) + norm + row, in dest-sorted order
__global__ void k_edge_enc(const int* __restrict__ ei,
                           const int* __restrict__ attr,
                           const float* __restrict__ bt) {
    int p = blockIdx.x * 8 + (threadIdx.x >> 5);
    if (p >= EE) return;
    int lane = threadIdx.x & 31;
    int e = g_perm[p];
    int r = ei[e], c = ei[EE + e];
    float4 acc = make_float4(0.f, 0.f, 0.f, 0.f);
#pragma unroll
    for (int cc = 0; cc < 3; cc++) {
        int idx = attr[e * 3 + cc];
        const float4* t = (const float4*)(bt + ((size_t)cc * 10 + idx) * DD);
        float4 v = t[lane];
        acc.x += v.x; acc.y += v.y; acc.z += v.z; acc.w += v.w;
    }
    __half2 p0 = __floats2half2_rn(acc.x, acc.y);
    __half2 p1 = __floats2half2_rn(acc.z, acc.w);
    uint2 packed = make_uint2(*(unsigned*)&p0, *(unsigned*)&p1);
    ((uint2*)g_ee16)[(size_t)p * 32 + lane] = packed;
    if (lane == 0) {
        g_rows[p] = r;
        g_norm[p] = g_dis[r] * g_dis[c];
    }
}

// ---------------- GEMM (tf32 mma.sync) with fused BN-in ----------------
// MODE 0: in = g_h (raw).  MODE 1: in = bn_relu(g_agg) (in-place safe), also -> hbuf.
// out: hl16 = fp16(in @ W^T + b)
template <int MODE>
__global__ __launch_bounds__(256, 2)
void k_gemm(const float* __restrict__ Wl, const float* __restrict__ bl,
            float* __restrict__ hbuf) {
    extern __shared__ unsigned smem_u[];
    unsigned* As = smem_u;             // [64][AS]
    unsigned* Bs = smem_u + 64 * AS;   // [128][AS]
    int tid = threadIdx.x;
    int row0 = blockIdx.x * 64;        // NN = 64 * 3125 exactly

    if (blockIdx.x == 0 && tid < DD) { g_sum[tid] = 0.0; g_sq[tid] = 0.0; }

    const float4* src4 = (const float4*)(MODE ? g_agg : g_h) + (size_t)row0 * 32;
    for (int i = tid; i < 64 * 32; i += 256) {
        int r = i >> 5, c4 = i & 31;
        float4 v = src4[(size_t)r * 32 + c4];
        if (MODE) {
            float4 sc = ((const float4*)g_scale)[c4];
            float4 sf = ((const float4*)g_shift)[c4];
            v.x = fmaxf(fmaf(v.x, sc.x, sf.x), 0.f);
            v.y = fmaxf(fmaf(v.y, sc.y, sf.y), 0.f);
            v.z = fmaxf(fmaf(v.z, sc.z, sf.z), 0.f);
            v.w = fmaxf(fmaf(v.w, sc.w, sf.w), 0.f);
            ((float4*)hbuf)[(size_t)(row0 + r) * 32 + c4] = v;
        }
        unsigned u0, u1, u2, u3;
        asm("cvt.rna.tf32.f32 %0, %1;" : "=r"(u0) : "f"(v.x));
        asm("cvt.rna.tf32.f32 %0, %1;" : "=r"(u1) : "f"(v.y));
        asm("cvt.rna.tf32.f32 %0, %1;" : "=r"(u2) : "f"(v.z));
        asm("cvt.rna.tf32.f32 %0, %1;" : "=r"(u3) : "f"(v.w));
        *(uint4*)&As[r * AS + c4 * 4] = make_uint4(u0, u1, u2, u3);
    }
    const float4* Wg4 = (const float4*)Wl;
    for (int i = tid; i < 128 * 32; i += 256) {
        int c4 = i & 31;
        float4 v = Wg4[i];
        unsigned u0, u1, u2, u3;
        asm("cvt.rna.tf32.f32 %0, %1;" : "=r"(u0) : "f"(v.x));
        asm("cvt.rna.tf32.f32 %0, %1;" : "=r"(u1) : "f"(v.y));
        asm("cvt.rna.tf32.f32 %0, %1;" : "=r"(u2) : "f"(v.z));
        asm("cvt.rna.tf32.f32 %0, %1;" : "=r"(u3) : "f"(v.w));
        *(uint4*)&Bs[(i >> 5) * AS + c4 * 4] = make_uint4(u0, u1, u2, u3);
    }
    __syncthreads();

    int w = tid >> 5, lane = tid & 31;
    int g = lane >> 2, tig = lane & 3;
    int rbase = (w & 3) * 16;
    int cbase = (w >> 2) * 64;

    float acc[8][4];
#pragma unroll
    for (int j = 0; j < 8; j++)
#pragma unroll
        for (int q = 0; q < 4; q++) acc[j][q] = 0.f;

#pragma unroll
    for (int ks = 0; ks < 16; ks++) {
        int k0 = ks * 8;
        unsigned a0 = As[(rbase + g) * AS + k0 + tig];
        unsigned a1 = As[(rbase + g + 8) * AS + k0 + tig];
        unsigned a2 = As[(rbase + g) * AS + k0 + tig + 4];
        unsigned a3 = As[(rbase + g + 8) * AS + k0 + tig + 4];
#pragma unroll
        for (int j = 0; j < 8; j++) {
            unsigned b0 = Bs[(cbase + j * 8 + g) * AS + k0 + tig];
            unsigned b1 = Bs[(cbase + j * 8 + g) * AS + k0 + tig + 4];
            asm("mma.sync.aligned.m16n8k8.row.col.f32.tf32.tf32.f32 "
                "{%0,%1,%2,%3},{%4,%5,%6,%7},{%8,%9},{%0,%1,%2,%3};"
                : "+f"(acc[j][0]), "+f"(acc[j][1]), "+f"(acc[j][2]), "+f"(acc[j][3])
                : "r"(a0), "r"(a1), "r"(a2), "r"(a3), "r"(b0), "r"(b1));
        }
    }

    int r0g = row0 + rbase + g;
    int r1g = r0g + 8;
#pragma unroll
    for (int j = 0; j < 8; j++) {
        int c0 = cbase + j * 8 + tig * 2;
        float bb0 = bl[c0], bb1 = bl[c0 + 1];
        __half2 h0 = __floats2half2_rn(acc[j][0] + bb0, acc[j][1] + bb1);
        __half2 h1 = __floats2half2_rn(acc[j][2] + bb0, acc[j][3] + bb1);
        *(__half2*)&g_hl16[(size_t)r0g * DD + c0] = h0;
        *(__half2*)&g_hl16[(size_t)r1g * DD + c0] = h1;
    }
}

// ---------------- fused: aggregate (CSR by dest, no atomics) + BN stats ----------------
// agg[c] = relu(hl[c]+root)*invdeg + sum_{p in [off[c],off[c+1])} norm[p]*relu(hl[rows[p]]+ee[p])
__global__ void k_msg_fused(const float* __restrict__ rootl) {
    int tid = threadIdx.x;
    int lane = tid & 31;
    int wraw = tid >> 5;
    int gw = blockIdx.x * 8 + wraw;
    const int TOTW = MSG_BLOCKS * 8;
    const int chunk = (NN + TOTW - 1) / TOTW;
    int c0 = gw * chunk;
    int c1 = c0 + chunk; if (c1 > NN) c1 = NN;

    float4 r4 = ((const float4*)rootl)[lane];
    float s0 = 0.f, s1 = 0.f, s2 = 0.f, s3 = 0.f;
    float q0 = 0.f, q1 = 0.f, q2 = 0.f, q3 = 0.f;
    const uint2* hl2 = (const uint2*)g_hl16;   // 32 uint2 per row
    const uint2* ee2 = (const uint2*)g_ee16;
    float4* agg4 = (float4*)g_agg;

    for (int c = c0; c < c1; c++) {
        float idg = g_invdeg[c];
        uint2 hraw = hl2[(size_t)c * 32 + lane];
        float2 f01 = __half22float2(*(__half2*)&hraw.x);
        float2 f23 = __half22float2(*(__half2*)&hraw.y);
        float4 o;
        o.x = fmaxf(f01.x + r4.x, 0.f) * idg;
        o.y = fmaxf(f01.y + r4.y, 0.f) * idg;
        o.z = fmaxf(f23.x + r4.z, 0.f) * idg;
        o.w = fmaxf(f23.y + r4.w, 0.f) * idg;
        int e0 = g_off[c], e1 = g_off[c + 1];
        for (int p = e0; p < e1; p++) {
            int r = g_rows[p];
            float nrm = g_norm[p];
            uint2 hh = hl2[(size_t)r * 32 + lane];
            uint2 em = ee2[(size_t)p * 32 + lane];
            float2 h01 = __half22float2(*(__half2*)&hh.x);
            float2 h23 = __half22float2(*(__half2*)&hh.y);
            float2 e01 = __half22float2(*(__half2*)&em.x);
            float2 e23 = __half22float2(*(__half2*)&em.y);
            o.x = fmaf(nrm, fmaxf(h01.x + e01.x, 0.f), o.x);
            o.y = fmaf(nrm, fmaxf(h01.y + e01.y, 0.f), o.y);
            o.z = fmaf(nrm, fmaxf(h23.x + e23.x, 0.f), o.z);
            o.w = fmaf(nrm, fmaxf(h23.y + e23.y, 0.f), o.w);
        }
        agg4[(size_t)c * 32 + lane] = o;
        s0 += o.x; s1 += o.y; s2 += o.z; s3 += o.w;
        q0 += o.x * o.x; q1 += o.y * o.y; q2 += o.z * o.z; q3 += o.w * o.w;
    }

    __shared__ float sh[256][4];
    sh[tid][0] = s0; sh[tid][1] = s1; sh[tid][2] = s2; sh[tid][3] = s3;
    __syncthreads();
    if (wraw == 0) {
        float t0 = 0.f, t1 = 0.f, t2 = 0.f, t3 = 0.f;
#pragma unroll
        for (int g = 0; g < 8; g++) {
            t0 += sh[g * 32 + lane][0];
            t1 += sh[g * 32 + lane][1];
            t2 += sh[g * 32 + lane][2];
            t3 += sh[g * 32 + lane][3];
        }
        atomicAdd(&g_sum[lane * 4 + 0], (double)t0);
        atomicAdd(&g_sum[lane * 4 + 1], (double)t1);
        atomicAdd(&g_sum[lane * 4 + 2], (double)t2);
        atomicAdd(&g_sum[lane * 4 + 3], (double)t3);
    }
    __syncthreads();
    sh[tid][0] = q0; sh[tid][1] = q1; sh[tid][2] = q2; sh[tid][3] = q3;
    __syncthreads();
    if (wraw == 0) {
        float t0 = 0.f, t1 = 0.f, t2 = 0.f, t3 = 0.f;
#pragma unroll
        for (int g = 0; g < 8; g++) {
            t0 += sh[g * 32 + lane][0];
            t1 += sh[g * 32 + lane][1];
            t2 += sh[g * 32 + lane][2];
            t3 += sh[g * 32 + lane][3];
        }
        atomicAdd(&g_sq[lane * 4 + 0], (double)t0);
        atomicAdd(&g_sq[lane * 4 + 1], (double)t1);
        atomicAdd(&g_sq[lane * 4 + 2], (double)t2);
        atomicAdd(&g_sq[lane * 4 + 3], (double)t3);
    }
}

__global__ void k_bn_prep(const float* __restrict__ gammal,
                          const float* __restrict__ betal) {
    int c = threadIdx.x;
    double mean = g_sum[c] / (double)NN;
    double var = g_sq[c] / (double)NN - mean * mean;
    if (var < 0.0) var = 0.0;
    float inv = rsqrtf((float)var + BN_EPS);
    float sc = gammal[c] * inv;
    g_scale[c] = sc;
    g_shift[c] = betal[c] - (float)mean * sc;
}

// final: out += h1..h4 + bn(agg_last) (no relu)
__global__ void k_total(float* __restrict__ out) {
    size_t idx = (size_t)blockIdx.x * blockDim.x + threadIdx.x;  // NN*32 float4s
    int lane = idx & 31;
    float4 a = ((const float4*)g_agg)[idx];
    float4 sc = ((const float4*)g_scale)[lane];
    float4 sf = ((const float4*)g_shift)[lane];
    float4 t = ((const float4*)out)[idx];
    t.x += fmaf(a.x, sc.x, sf.x);
    t.y += fmaf(a.y, sc.y, sf.y);
    t.z += fmaf(a.z, sc.z, sf.z);
    t.w += fmaf(a.w, sc.w, sf.w);
    const float4* hb = (const float4*)g_hbuf;
    size_t stride = (size_t)NN * 32;
#pragma unroll
    for (int l = 0; l < 4; l++) {
        float4 v = hb[idx + stride * l];
        t.x += v.x; t.y += v.y; t.z += v.z; t.w += v.w;
    }
    ((float4*)out)[idx] = t;
}

// ---------------- launch ----------------
extern "C" void kernel_launch(void* const* d_in, const int* in_sizes, int n_in,
                              void* d_out, int out_size) {
    const int*   x     = (const int*)d_in[0];
    const int*   ei    = (const int*)d_in[1];
    const int*   attr  = (const int*)d_in[2];
    const float* at    = (const float*)d_in[3];
    const float* bt    = (const float*)d_in[4];
    const float* W     = (const float*)d_in[5];
    const float* b     = (const float*)d_in[6];
    const float* root  = (const float*)d_in[7];
    const float* gamma = (const float*)d_in[8];
    const float* beta  = (const float*)d_in[9];
    float* out = (float*)d_out;

    cudaFuncSetAttribute(k_gemm<0>, cudaFuncAttributeMaxDynamicSharedMemorySize, GEMM_SMEM);
    cudaFuncSetAttribute(k_gemm<1>, cudaFuncAttributeMaxDynamicSharedMemorySize, GEMM_SMEM);

    k_node_enc<<<NN / 8, 256>>>(x, at, out);
    k_deg_init<<<(NN + 255) / 256, 256>>>();
    k_deg_count<<<(EE + 255) / 256, 256>>>(ei);
    k_dis<<<(NN + 255) / 256, 256>>>();
    k_scan1<<<SCAN_NBLK, SCAN_BLK>>>();
    k_scan2<<<1, SCAN_BLK>>>();
    k_scan3<<<(NN + 255) / 256, 256>>>();
    k_scatter<<<(EE + 255) / 256, 256>>>(ei);
    k_edge_enc<<<EE / 8, 256>>>(ei, attr, bt);

    float* hbuf = (float*)nullptr;
    cudaGetSymbolAddress((void**)&hbuf, g_hbuf);
    for (int l = 0; l < LL; l++) {
        const float* Wl = W + (size_t)l * DD * DD;
        const float* bl = b + (size_t)l * DD;
        if (l == 0) {
            k_gemm<0><<<NN / 64, 256, GEMM_SMEM>>>(Wl, bl, nullptr);
        } else {
            k_gemm<1><<<NN / 64, 256, GEMM_SMEM>>>(Wl, bl,
                                                   hbuf + (size_t)(l - 1) * NN * DD);
        }
        k_msg_fused<<<MSG_BLOCKS, 256>>>(root + (size_t)l * DD);
        k_bn_prep<<<1, 128>>>(gamma + (size_t)l * DD, beta + (size_t)l * DD);
    }
    k_total<<<NN * 32 / 256, 256>>>(out);
}